// round 1
// baseline (speedup 1.0000x reference)
#include <cuda_runtime.h>

#define B_  8
#define NK_ 2048
#define NQ_ 2048
#define D_  256
#define H_  1024

// ---------------- scratch (device globals: no allocations allowed) ----------------
__device__ float g_P [(size_t)B_*NK_*D_];    // K @ G        [b, i, c']   16 MiB
__device__ float g_S [(size_t)B_*NK_*NQ_];   // logits/weights [b, i, k]  128 MiB
__device__ float g_Z [(size_t)B_*NK_*D_];    // Wv @ lin_w^T  [b, i, d]   16 MiB
__device__ float g_Gt[D_*D_];                // Gt[c',c] = sum_h Wq_w[h,c'] Wk_w[h,c]
__device__ float g_M2[D_*D_];                // M2[d,c]  = sum_h lin_w[d,h] Wv_w[h,c]
__device__ float g_linT[H_*D_];              // lin_w transposed [h, d]
__device__ float g_gv[D_];                   // g[c] = sum_h Wk_b[h] Wq_w[h,c]
__device__ float g_cv[D_];                   // cv[d] = sum_h lin_w[d,h] Wv_b[h]
__device__ float g_v [B_*NQ_];               // v[b,k] = Q[b,k,:] . g

// ---------------- tiny precompute kernels ----------------
__global__ void transpose_lin(const float* __restrict__ lin_w) {
    int idx = blockIdx.x * 256 + threadIdx.x;     // [0, H_*D_)
    int h = idx >> 8, d = idx & 255;
    g_linT[h * D_ + d] = lin_w[d * H_ + h];
}

__global__ void vec_pre(const float* __restrict__ Wk_b, const float* __restrict__ Wq_w,
                        const float* __restrict__ lin_w, const float* __restrict__ Wv_b) {
    int t = threadIdx.x;  // 0..255
    if (blockIdx.x == 0) {
        float s = 0.f;
        for (int h = 0; h < H_; ++h) s += Wk_b[h] * Wq_w[h * D_ + t];
        g_gv[t] = s;
    } else {
        float s = 0.f;
        for (int h = 0; h < H_; ++h) s += lin_w[t * H_ + h] * Wv_b[h];
        g_cv[t] = s;
    }
}

// 256x256 = A^T(KxM) * B(KxN), K=1024.  z=0: Gt = Wq_w^T Wk_w ; z=1: M2 = linT^T Wv_w
__global__ void small_gemm_tn(const float* __restrict__ Wq_w,
                              const float* __restrict__ Wk_w,
                              const float* __restrict__ Wv_w) {
    const float *A, *Bm; float* C;
    if (blockIdx.z == 0) { A = Wq_w;  Bm = Wk_w; C = g_Gt; }
    else                 { A = g_linT; Bm = Wv_w; C = g_M2; }
    __shared__ float As[16][33], Bs[16][33];
    int tid = threadIdx.x, tx = tid & 15, ty = tid >> 4;
    int m0 = blockIdx.x * 32, n0 = blockIdx.y * 32;
    float acc[2][2] = {};
    for (int k0 = 0; k0 < H_; k0 += 16) {
        #pragma unroll
        for (int p = 0; p < 2; ++p) {
            int e = tid + p * 256; int kk = e >> 5, mm = e & 31;
            As[kk][mm] = A [(k0 + kk) * D_ + m0 + mm];
            Bs[kk][mm] = Bm[(k0 + kk) * D_ + n0 + mm];
        }
        __syncthreads();
        #pragma unroll
        for (int kk = 0; kk < 16; ++kk) {
            float a0 = As[kk][ty*2], a1 = As[kk][ty*2+1];
            float b0 = Bs[kk][tx*2], b1 = Bs[kk][tx*2+1];
            acc[0][0] += a0*b0; acc[0][1] += a0*b1;
            acc[1][0] += a1*b0; acc[1][1] += a1*b1;
        }
        __syncthreads();
    }
    #pragma unroll
    for (int i = 0; i < 2; ++i)
        #pragma unroll
        for (int j = 0; j < 2; ++j)
            C[(m0 + ty*2 + i) * D_ + n0 + tx*2 + j] = acc[i][j];
}

// v[b,k] = Q[b,k,:] . g   (one warp per row)
__global__ void qdotg(const float* __restrict__ Q) {
    int gw   = (blockIdx.x * blockDim.x + threadIdx.x) >> 5;  // global warp = b*NQ+k
    int lane = threadIdx.x & 31;
    const float* q = Q + (size_t)gw * D_;
    float s = 0.f;
    for (int t = lane; t < D_; t += 32) s += q[t] * g_gv[t];
    #pragma unroll
    for (int o = 16; o; o >>= 1) s += __shfl_xor_sync(0xffffffffu, s, o);
    if (!lane) g_v[gw] = s;
}

// ---------------- main tiled GEMM: C[M,N] (+bias[n]) ----------------
// TN=false: C = A[M,K] * B[N,K]^T   (both K-major)
// TN=true : C = Asrc[K,M]^T * B[K,N]
template <bool TN>
__global__ __launch_bounds__(256, 2)
void gemm128(const float* __restrict__ A, const float* __restrict__ Bm,
             float* __restrict__ C,
             int lda, int ldb, int ldc, int K,
             size_t sA, size_t sB, size_t sC,
             const float* __restrict__ bias) {
    A  += (size_t)blockIdx.z * sA;
    Bm += (size_t)blockIdx.z * sB;
    C  += (size_t)blockIdx.z * sC;
    __shared__ float As[8][132], Bs[8][132];
    int tid = threadIdx.x, tx = tid & 15, ty = tid >> 4;
    int m0 = blockIdx.x * 128, n0 = blockIdx.y * 128;
    float acc[8][8] = {};
    for (int k0 = 0; k0 < K; k0 += 8) {
        #pragma unroll
        for (int p = 0; p < 4; ++p) {
            int e = tid + p * 256;
            if (TN) {
                int kk = e >> 7, mm = e & 127;
                As[kk][mm] = A [(size_t)(k0 + kk) * lda + m0 + mm];
                Bs[kk][mm] = Bm[(size_t)(k0 + kk) * ldb + n0 + mm];
            } else {
                int kk = e & 7, mm = e >> 3;
                As[kk][mm] = A [(size_t)(m0 + mm) * lda + k0 + kk];
                Bs[kk][mm] = Bm[(size_t)(n0 + mm) * ldb + k0 + kk];
            }
        }
        __syncthreads();
        #pragma unroll
        for (int kk = 0; kk < 8; ++kk) {
            float a[8], b[8];
            #pragma unroll
            for (int j = 0; j < 8; ++j) { a[j] = As[kk][ty*8 + j]; b[j] = Bs[kk][tx*8 + j]; }
            #pragma unroll
            for (int i = 0; i < 8; ++i)
                #pragma unroll
                for (int j = 0; j < 8; ++j)
                    acc[i][j] += a[i] * b[j];
        }
        __syncthreads();
    }
    #pragma unroll
    for (int i = 0; i < 8; ++i) {
        int row = m0 + ty*8 + i;
        #pragma unroll
        for (int j = 0; j < 8; ++j) {
            int col = n0 + tx*8 + j;
            float v = acc[i][j];
            if (bias) v += bias[col];
            C[(size_t)row * ldc + col] = v;
        }
    }
}

// ---------------- softmax over k of scale*(S[i,k] + v[k]), in place ----------------
__global__ void softmax_rows() {
    int b = blockIdx.y, i = blockIdx.x;
    float* row = g_S + ((size_t)b * NK_ + i) * NQ_;
    const float* vv = g_v + b * NQ_;
    int tid = threadIdx.x, lane = tid & 31, wid = tid >> 5;
    const float scale = 0.03125f;  // 1/sqrt(1024)
    float x[8]; float mx = -1e30f;
    #pragma unroll
    for (int j = 0; j < 8; ++j) {
        int k = tid + j * 256;
        float t = (row[k] + vv[k]) * scale;
        x[j] = t; mx = fmaxf(mx, t);
    }
    __shared__ float red[8];
    #pragma unroll
    for (int o = 16; o; o >>= 1) mx = fmaxf(mx, __shfl_xor_sync(0xffffffffu, mx, o));
    if (!lane) red[wid] = mx;
    __syncthreads();
    float bm = red[0];
    #pragma unroll
    for (int w = 1; w < 8; ++w) bm = fmaxf(bm, red[w]);
    float s = 0.f;
    #pragma unroll
    for (int j = 0; j < 8; ++j) { x[j] = __expf(x[j] - bm); s += x[j]; }
    __syncthreads();  // everyone done reading red[] (max phase)
    #pragma unroll
    for (int o = 16; o; o >>= 1) s += __shfl_xor_sync(0xffffffffu, s, o);
    if (!lane) red[wid] = s;
    __syncthreads();
    float bs = 0.f;
    #pragma unroll
    for (int w = 0; w < 8; ++w) bs += red[w];
    float inv = 1.0f / bs;
    #pragma unroll
    for (int j = 0; j < 8; ++j) row[tid + j * 256] = x[j] * inv;
}

// ---------------- launcher ----------------
extern "C" void kernel_launch(void* const* d_in, const int* in_sizes, int n_in,
                              void* d_out, int out_size) {
    const float* KEY   = (const float*)d_in[0];
    const float* VALUE = (const float*)d_in[1];
    const float* QUERY = (const float*)d_in[2];
    const float* Wk_w  = (const float*)d_in[3];
    const float* Wk_b  = (const float*)d_in[4];
    const float* Wq_w  = (const float*)d_in[5];
    /* Wq_b = d_in[6] — cancels exactly under softmax over k */
    const float* Wv_w  = (const float*)d_in[7];
    const float* Wv_b  = (const float*)d_in[8];
    const float* lin_w = (const float*)d_in[9];
    const float* lin_b = (const float*)d_in[10];
    float* out = (float*)d_out;

    float *pP, *pS, *pZ, *pGt, *pM2, *pcv;
    cudaGetSymbolAddress((void**)&pP,  g_P);
    cudaGetSymbolAddress((void**)&pS,  g_S);
    cudaGetSymbolAddress((void**)&pZ,  g_Z);
    cudaGetSymbolAddress((void**)&pGt, g_Gt);
    cudaGetSymbolAddress((void**)&pM2, g_M2);
    cudaGetSymbolAddress((void**)&pcv, g_cv);

    const size_t sBD = (size_t)NK_ * D_;   // per-batch stride for [2048,256] mats
    const size_t sSS = (size_t)NK_ * NQ_;  // per-batch stride for S

    // precomputes
    transpose_lin<<<H_ * D_ / 256, 256>>>(lin_w);
    vec_pre<<<2, 256>>>(Wk_b, Wq_w, lin_w, Wv_b);
    small_gemm_tn<<<dim3(8, 8, 2), 256>>>(Wq_w, Wk_w, Wv_w);
    qdotg<<<(B_ * NQ_) / 8, 256>>>(QUERY);

    // P = KEY @ Gt^T            [b,2048,256]
    gemm128<false><<<dim3(16, 2, B_), 256>>>(KEY, pGt, pP, D_, D_, D_, D_,
                                             sBD, 0, sBD, nullptr);
    // S = P @ QUERY^T           [b,2048,2048]
    gemm128<false><<<dim3(16, 16, B_), 256>>>(pP, QUERY, pS, D_, D_, NQ_, D_,
                                              sBD, sBD, sSS, nullptr);
    // weights = softmax_k(scale*(S + v)), in place
    softmax_rows<<<dim3(NK_, B_), 256>>>();
    // Z = VALUE @ M2^T + cv     [b,2048,256]
    gemm128<false><<<dim3(16, 2, B_), 256>>>(VALUE, pM2, pZ, D_, D_, D_, D_,
                                             sBD, 0, sBD, pcv);
    // res = weights^T @ Z + lin_b  -> d_out [b,2048,256]
    gemm128<true><<<dim3(16, 2, B_), 256>>>(pS, pZ, out, NQ_, D_, D_, NK_,
                                            sSS, sBD, sBD, lin_b);
}

// round 6
// speedup vs baseline: 1.8473x; 1.8473x over previous
#include <cuda_runtime.h>
#include <cuda_bf16.h>
#include <cstdint>

#define B_  8
#define NK_ 2048
#define NQ_ 2048
#define D_  256
#define H_  1024
#define KS3 768     // 3*256: split-K for D-dim GEMMs
#define KI3 6144    // 3*2048: split-K over i for the out GEMM

// ======================= low-level helpers =======================
__device__ __forceinline__ uint32_t smem_u32(const void* p) {
    uint32_t a;
    asm("{ .reg .u64 t; cvta.to.shared.u64 t, %1; cvt.u32.u64 %0, t; }" : "=r"(a) : "l"(p));
    return a;
}
#define CP16(sm, g) asm volatile("cp.async.cg.shared.global [%0], [%1], 16;" :: "r"(sm), "l"(g))
#define CP_COMMIT   asm volatile("cp.async.commit_group;" ::: "memory")
#define CP_WAIT0    asm volatile("cp.async.wait_group 0;" ::: "memory")

__device__ __forceinline__ void ldm_x4(uint32_t* r, uint32_t addr) {
    asm volatile("ldmatrix.sync.aligned.m8n8.x4.shared.b16 {%0,%1,%2,%3}, [%4];"
                 : "=r"(r[0]), "=r"(r[1]), "=r"(r[2]), "=r"(r[3]) : "r"(addr));
}
__device__ __forceinline__ void mma16816(float* c, const uint32_t* a, const uint32_t* b) {
    asm volatile("mma.sync.aligned.m16n8k16.row.col.f32.bf16.bf16.f32 "
                 "{%0,%1,%2,%3}, {%4,%5,%6,%7}, {%8,%9}, {%0,%1,%2,%3};"
                 : "+f"(c[0]), "+f"(c[1]), "+f"(c[2]), "+f"(c[3])
                 : "r"(a[0]), "r"(a[1]), "r"(a[2]), "r"(a[3]), "r"(b[0]), "r"(b[1]));
}

// ======================= scratch =======================
__device__ __align__(128) __nv_bfloat16 g_K2 [(size_t)B_*NK_*KS3];   // KEY   A-form [hi|lo|hi]
__device__ __align__(128) __nv_bfloat16 g_V2 [(size_t)B_*NK_*KS3];   // VALUE A-form
__device__ __align__(128) __nv_bfloat16 g_Q2 [(size_t)B_*NQ_*KS3];   // QUERY B-form [hi|hi|lo]
__device__ __align__(128) __nv_bfloat16 g_P2 [(size_t)B_*NK_*KS3];   // P     A-form
__device__ __align__(128) __nv_bfloat16 g_Zt2[(size_t)B_*D_*KI3];    // Z^T   B-form over i
__device__ __align__(128) __nv_bfloat16 g_Wt2[(size_t)B_*NQ_*KI3];   // W^T   A-form over i
__device__ __align__(128) float g_S [(size_t)B_*NK_*NQ_];            // logits fp32 [i,k]
__device__ __align__(128) float g_Z [(size_t)B_*NK_*D_];             // Z fp32 [i,d]
__device__ __align__(128) __nv_bfloat16 g_Gt2[D_*KS3];               // B-form
__device__ __align__(128) __nv_bfloat16 g_M22[D_*KS3];               // B-form
__device__ float g_Gt[D_*D_];
__device__ float g_M2[D_*D_];
__device__ float g_linT[H_*D_];
__device__ float g_gv[D_];
__device__ float g_cv[D_];
__device__ float g_v [B_*NQ_];
__device__ float g_m [B_*NK_];
__device__ float g_si[B_*NK_];

// ======================= tiny precompute =======================
__global__ void transpose_lin(const float* __restrict__ lin_w) {
    int idx = blockIdx.x * 256 + threadIdx.x;
    int h = idx >> 8, d = idx & 255;
    g_linT[h * D_ + d] = lin_w[d * H_ + h];
}
__global__ void vec_pre(const float* __restrict__ Wk_b, const float* __restrict__ Wq_w,
                        const float* __restrict__ lin_w, const float* __restrict__ Wv_b) {
    int t = threadIdx.x;
    if (blockIdx.x == 0) {
        float s = 0.f;
        for (int h = 0; h < H_; ++h) s += Wk_b[h] * Wq_w[h * D_ + t];
        g_gv[t] = s;
    } else {
        float s = 0.f;
        for (int h = 0; h < H_; ++h) s += lin_w[t * H_ + h] * Wv_b[h];
        g_cv[t] = s;
    }
}
// 256x256 = A^T(KxM)*B(KxN), K=1024. z=0: Gt = Wq_w^T Wk_w ; z=1: M2 = linT^T Wv_w
__global__ void small_gemm_tn(const float* __restrict__ Wq_w,
                              const float* __restrict__ Wk_w,
                              const float* __restrict__ Wv_w) {
    const float *A, *Bm; float* C;
    if (blockIdx.z == 0) { A = Wq_w;   Bm = Wk_w; C = g_Gt; }
    else                 { A = g_linT; Bm = Wv_w; C = g_M2; }
    __shared__ float As[16][33], Bs[16][33];
    int tid = threadIdx.x, tx = tid & 15, ty = tid >> 4;
    int m0 = blockIdx.x * 32, n0 = blockIdx.y * 32;
    float acc[2][2] = {};
    for (int k0 = 0; k0 < H_; k0 += 16) {
        #pragma unroll
        for (int p = 0; p < 2; ++p) {
            int e = tid + p * 256; int kk = e >> 5, mm = e & 31;
            As[kk][mm] = A [(k0 + kk) * D_ + m0 + mm];
            Bs[kk][mm] = Bm[(k0 + kk) * D_ + n0 + mm];
        }
        __syncthreads();
        #pragma unroll
        for (int kk = 0; kk < 16; ++kk) {
            float a0 = As[kk][ty*2], a1 = As[kk][ty*2+1];
            float b0 = Bs[kk][tx*2], b1 = Bs[kk][tx*2+1];
            acc[0][0] += a0*b0; acc[0][1] += a0*b1;
            acc[1][0] += a1*b0; acc[1][1] += a1*b1;
        }
        __syncthreads();
    }
    #pragma unroll
    for (int i = 0; i < 2; ++i)
        #pragma unroll
        for (int j = 0; j < 2; ++j)
            C[(m0 + ty*2 + i) * D_ + n0 + tx*2 + j] = acc[i][j];
}
__global__ void qdotg(const float* __restrict__ Q) {
    int gw   = (blockIdx.x * blockDim.x + threadIdx.x) >> 5;
    int lane = threadIdx.x & 31;
    const float* q = Q + (size_t)gw * D_;
    float s = 0.f;
    for (int t = lane; t < D_; t += 32) s += q[t] * g_gv[t];
    #pragma unroll
    for (int o = 16; o; o >>= 1) s += __shfl_xor_sync(0xffffffffu, s, o);
    if (!lane) g_v[gw] = s;
}

// fp32 [rows,256] -> 3-block split [rows,768].  AFORM: [hi|lo|hi]  else [hi|hi|lo]
template<bool AFORM>
__global__ void split_rows(const float* __restrict__ X, __nv_bfloat16* __restrict__ Y) {
    size_t idx = (size_t)blockIdx.x * 256 + threadIdx.x;
    size_t row = idx >> 8; int c = (int)(idx & 255);
    float x = X[idx];
    __nv_bfloat16 hi = __float2bfloat16(x);
    __nv_bfloat16 lo = __float2bfloat16(x - __bfloat162float(hi));
    __nv_bfloat16* r = Y + row * KS3 + c;
    r[0] = hi;
    if (AFORM) { r[256] = lo; r[512] = hi; }
    else       { r[256] = hi; r[512] = lo; }
}

// ======================= HMMA GEMM: C[M,N] = A[M,K] * B[N,K]^T =======================
// 128x128 block tile, BK=32, 8 warps (2 M x 4 N), warp tile 64x32, mma m16n8k16.
// EPI 0: fp32 store (+opt bias[col]), ldc given.
// EPI 2: 3-block A-form split store to [row*KS3 + col] (hi), +256 (lo), +512 (hi).
template<int EPI>
__global__ __launch_bounds__(256, 2)
void mma_gemm(const __nv_bfloat16* __restrict__ A, const __nv_bfloat16* __restrict__ Bm,
              void* __restrict__ dst, const float* __restrict__ bias,
              int Ktot, size_t sA, size_t sB, size_t sD, int ldc)
{
    __shared__ __align__(16) char smA[2][128 * 80];
    __shared__ __align__(16) char smB[2][128 * 80];
    int tid = threadIdx.x, wid = tid >> 5, lane = tid & 31;
    int b = blockIdx.z;
    int m0 = blockIdx.x * 128, n0 = blockIdx.y * 128;
    A  += (size_t)b * sA;
    Bm += (size_t)b * sB;
    const int wm = wid & 1, wn = wid >> 1;
    float acc[4][4][4] = {};

    auto issue = [&](int c, int buf) {
        #pragma unroll
        for (int it = 0; it < 2; ++it) {
            int e = tid + it * 256;          // 0..511
            int r = e >> 2, q = e & 3;
            const __nv_bfloat16* ga = A  + (size_t)(m0 + r) * Ktot + c * 32 + q * 8;
            const __nv_bfloat16* gb = Bm + (size_t)(n0 + r) * Ktot + c * 32 + q * 8;
            CP16(smem_u32(&smA[buf][r * 80 + q * 16]), ga);
            CP16(smem_u32(&smB[buf][r * 80 + q * 16]), gb);
        }
    };

    const int nc = Ktot >> 5;
    issue(0, 0); CP_COMMIT;
    int buf = 0;
    for (int c = 0; c < nc; ++c) {
        CP_WAIT0;
        __syncthreads();
        if (c + 1 < nc) { issue(c + 1, buf ^ 1); CP_COMMIT; }
        #pragma unroll
        for (int ks = 0; ks < 2; ++ks) {
            uint32_t a[4][4], bb[4][2];
            #pragma unroll
            for (int t = 0; t < 4; ++t) {
                uint32_t addr = smem_u32(&smA[buf][(wm * 64 + t * 16 + (lane & 15)) * 80
                                                   + ks * 32 + ((lane >> 4) << 4)]);
                ldm_x4(a[t], addr);
            }
            #pragma unroll
            for (int u2 = 0; u2 < 2; ++u2) {
                uint32_t row = wn * 32 + u2 * 16 + ((lane >> 4) << 3) + (lane & 7);
                uint32_t koff = ks * 32 + (((lane >> 3) & 1) << 4);
                uint32_t r4[4];
                ldm_x4(r4, smem_u32(&smB[buf][row * 80 + koff]));
                bb[u2*2][0] = r4[0]; bb[u2*2][1] = r4[1];
                bb[u2*2+1][0] = r4[2]; bb[u2*2+1][1] = r4[3];
            }
            #pragma unroll
            for (int t = 0; t < 4; ++t)
                #pragma unroll
                for (int u = 0; u < 4; ++u)
                    mma16816(acc[t][u], a[t], bb[u]);
        }
        buf ^= 1;
    }

    // epilogue: lane l holds rows (g, g+8), cols (q*2, q*2+1) per tile; g=l>>2, q=l&3
    #pragma unroll
    for (int t = 0; t < 4; ++t) {
        int r0 = m0 + wm * 64 + t * 16 + (lane >> 2);
        #pragma unroll
        for (int u = 0; u < 4; ++u) {
            int cc = n0 + wn * 32 + u * 8 + (lane & 3) * 2;
            float x0 = acc[t][u][0], x1 = acc[t][u][1];
            float x2 = acc[t][u][2], x3 = acc[t][u][3];
            if (EPI == 0) {
                float* C = (float*)dst + (size_t)b * sD;
                float b0 = bias ? bias[cc] : 0.f, b1 = bias ? bias[cc + 1] : 0.f;
                float2 v0 = {x0 + b0, x1 + b1};
                float2 v1 = {x2 + b0, x3 + b1};
                *(float2*)&C[(size_t)r0 * ldc + cc]       = v0;
                *(float2*)&C[(size_t)(r0 + 8) * ldc + cc] = v1;
            } else {
                __nv_bfloat16* Y = (__nv_bfloat16*)dst + (size_t)b * sD;
                #pragma unroll
                for (int h = 0; h < 2; ++h) {
                    int row = r0 + h * 8;
                    float y0 = h ? x2 : x0, y1 = h ? x3 : x1;
                    __nv_bfloat16 h0 = __float2bfloat16(y0);
                    __nv_bfloat16 h1 = __float2bfloat16(y1);
                    __nv_bfloat16 l0 = __float2bfloat16(y0 - __bfloat162float(h0));
                    __nv_bfloat16 l1 = __float2bfloat16(y1 - __bfloat162float(h1));
                    __nv_bfloat162 hp; hp.x = h0; hp.y = h1;
                    __nv_bfloat162 lp; lp.x = l0; lp.y = l1;
                    *(__nv_bfloat162*)&Y[(size_t)row * KS3 + cc]       = hp;
                    *(__nv_bfloat162*)&Y[(size_t)row * KS3 + 256 + cc] = lp;
                    *(__nv_bfloat162*)&Y[(size_t)row * KS3 + 512 + cc] = hp;
                }
            }
        }
    }
}

// ======================= softmax stats =======================
__global__ void softmax_stats() {
    int b = blockIdx.y, i = blockIdx.x;
    const float* row = g_S + ((size_t)b * NK_ + i) * NQ_;
    const float* vv  = g_v + b * NQ_;
    int tid = threadIdx.x, lane = tid & 31, wid = tid >> 5;
    const float scale = 0.03125f;
    float x[8]; float mx = -1e30f;
    #pragma unroll
    for (int j = 0; j < 8; ++j) {
        int k = tid + j * 256;
        float t = (row[k] + vv[k]) * scale;
        x[j] = t; mx = fmaxf(mx, t);
    }
    __shared__ float red[8];
    #pragma unroll
    for (int o = 16; o; o >>= 1) mx = fmaxf(mx, __shfl_xor_sync(0xffffffffu, mx, o));
    if (!lane) red[wid] = mx;
    __syncthreads();
    float bm = red[0];
    #pragma unroll
    for (int w = 1; w < 8; ++w) bm = fmaxf(bm, red[w]);
    float s = 0.f;
    #pragma unroll
    for (int j = 0; j < 8; ++j) s += __expf(x[j] - bm);
    __syncthreads();
    #pragma unroll
    for (int o = 16; o; o >>= 1) s += __shfl_xor_sync(0xffffffffu, s, o);
    if (!lane) red[wid] = s;
    __syncthreads();
    if (tid == 0) {
        float bs = 0.f;
        #pragma unroll
        for (int w = 0; w < 8; ++w) bs += red[w];
        g_m [b * NK_ + i] = bm;
        g_si[b * NK_ + i] = 1.0f / bs;
    }
}

// W^T A-form build: row k, [i]=hi, [2048+i]=lo, [4096+i]=hi
__global__ void build_wt() {
    __shared__ float sm[32][33];
    __shared__ float smm[32], sms[32], smv[32];
    int b = blockIdx.z;
    int i0 = blockIdx.x * 32, k0 = blockIdx.y * 32;
    int tx = threadIdx.x, ty = threadIdx.y;
    const float* S = g_S + (size_t)b * NK_ * NQ_;
    #pragma unroll
    for (int t = 0; t < 4; ++t)
        sm[ty + 8 * t][tx] = S[(size_t)(i0 + ty + 8 * t) * NQ_ + k0 + tx];
    if (ty == 0) { smm[tx] = g_m[b * NK_ + i0 + tx]; sms[tx] = g_si[b * NK_ + i0 + tx]; }
    if (ty == 1) { smv[tx] = g_v[b * NQ_ + k0 + tx]; }
    __syncthreads();
    __nv_bfloat16* W = g_Wt2 + (size_t)b * NQ_ * KI3;
    const float scale = 0.03125f;
    #pragma unroll
    for (int t = 0; t < 4; ++t) {
        int kl = ty + 8 * t;
        float w = __expf((sm[tx][kl] + smv[kl]) * scale - smm[tx]) * sms[tx];
        __nv_bfloat16 hi = __float2bfloat16(w);
        __nv_bfloat16 lo = __float2bfloat16(w - __bfloat162float(hi));
        __nv_bfloat16* r = W + (size_t)(k0 + kl) * KI3 + i0 + tx;
        r[0] = hi; r[2048] = lo; r[4096] = hi;
    }
}

// Z fp32 [i,256] -> Zt2 B-form [d, 6144]: [i]=hi, [2048+i]=hi, [4096+i]=lo
__global__ void transpose_split_z() {
    __shared__ float sm[32][33];
    int b = blockIdx.z;
    int i0 = blockIdx.x * 32, d0 = blockIdx.y * 32;
    int tx = threadIdx.x, ty = threadIdx.y;
    const float* Z = g_Z + (size_t)b * NK_ * D_;
    #pragma unroll
    for (int t = 0; t < 4; ++t)
        sm[ty + 8 * t][tx] = Z[(size_t)(i0 + ty + 8 * t) * D_ + d0 + tx];
    __syncthreads();
    __nv_bfloat16* Y = g_Zt2 + (size_t)b * D_ * KI3;
    #pragma unroll
    for (int t = 0; t < 4; ++t) {
        int d = d0 + ty + 8 * t, i = i0 + tx;
        float x = sm[tx][ty + 8 * t];
        __nv_bfloat16 hi = __float2bfloat16(x);
        __nv_bfloat16 lo = __float2bfloat16(x - __bfloat162float(hi));
        __nv_bfloat16* r = Y + (size_t)d * KI3 + i;
        r[0] = hi; r[2048] = hi; r[4096] = lo;
    }
}

// ======================= launcher =======================
extern "C" void kernel_launch(void* const* d_in, const int* in_sizes, int n_in,
                              void* d_out, int out_size) {
    const float* KEY   = (const float*)d_in[0];
    const float* VALUE = (const float*)d_in[1];
    const float* QUERY = (const float*)d_in[2];
    const float* Wk_w  = (const float*)d_in[3];
    const float* Wk_b  = (const float*)d_in[4];
    const float* Wq_w  = (const float*)d_in[5];
    /* Wq_b (d_in[6]) cancels exactly under softmax over k */
    const float* Wv_w  = (const float*)d_in[7];
    const float* Wv_b  = (const float*)d_in[8];
    const float* lin_w = (const float*)d_in[9];
    const float* lin_b = (const float*)d_in[10];
    float* out = (float*)d_out;

    __nv_bfloat16 *pK2, *pV2, *pQ2, *pP2, *pZt2, *pWt2, *pGt2, *pM22;
    float *pS, *pZ, *pGt, *pM2, *pcv;
    cudaGetSymbolAddress((void**)&pK2,  g_K2);
    cudaGetSymbolAddress((void**)&pV2,  g_V2);
    cudaGetSymbolAddress((void**)&pQ2,  g_Q2);
    cudaGetSymbolAddress((void**)&pP2,  g_P2);
    cudaGetSymbolAddress((void**)&pZt2, g_Zt2);
    cudaGetSymbolAddress((void**)&pWt2, g_Wt2);
    cudaGetSymbolAddress((void**)&pGt2, g_Gt2);
    cudaGetSymbolAddress((void**)&pM22, g_M22);
    cudaGetSymbolAddress((void**)&pS,   g_S);
    cudaGetSymbolAddress((void**)&pZ,   g_Z);
    cudaGetSymbolAddress((void**)&pGt,  g_Gt);
    cudaGetSymbolAddress((void**)&pM2,  g_M2);
    cudaGetSymbolAddress((void**)&pcv,  g_cv);

    const size_t sRow = (size_t)NK_ * KS3;   // [2048,768] bf16 batch stride
    const size_t sZt  = (size_t)D_ * KI3;    // [256,6144]
    const size_t sWt  = (size_t)NQ_ * KI3;   // [2048,6144]
    const size_t sS   = (size_t)NK_ * NQ_;
    const size_t sZ   = (size_t)NK_ * D_;
    const size_t sOut = (size_t)NQ_ * D_;

    // precompute
    transpose_lin<<<H_ * D_ / 256, 256>>>(lin_w);
    vec_pre<<<2, 256>>>(Wk_b, Wq_w, lin_w, Wv_b);
    small_gemm_tn<<<dim3(8, 8, 2), 256>>>(Wq_w, Wk_w, Wv_w);
    qdotg<<<(B_ * NQ_) / 8, 256>>>(QUERY);

    // splits
    split_rows<true ><<<(B_ * NK_ * D_) / 256, 256>>>(KEY,   pK2);
    split_rows<true ><<<(B_ * NK_ * D_) / 256, 256>>>(VALUE, pV2);
    split_rows<false><<<(B_ * NQ_ * D_) / 256, 256>>>(QUERY, pQ2);
    split_rows<false><<<(D_ * D_) / 256, 256>>>(pGt, pGt2);
    split_rows<false><<<(D_ * D_) / 256, 256>>>(pM2, pM22);

    // P2 = split(KEY @ Gt^T)            [b,2048,768]  (A-form epilogue)
    mma_gemm<2><<<dim3(16, 2, B_), 256>>>(pK2, pGt2, pP2, nullptr,
                                          KS3, sRow, 0, sRow, 0);
    // Z = VALUE @ M2^T + cv             [b,2048,256] fp32
    mma_gemm<0><<<dim3(16, 2, B_), 256>>>(pV2, pM22, pZ, pcv,
                                          KS3, sRow, 0, sZ, D_);
    // S = P @ Q^T                       [b,2048,2048] fp32
    mma_gemm<0><<<dim3(16, 16, B_), 256>>>(pP2, pQ2, pS, nullptr,
                                           KS3, sRow, sRow, sS, NQ_);
    // softmax stats + W^T build + Z^T build
    softmax_stats<<<dim3(NK_, B_), 256>>>();
    build_wt<<<dim3(64, 64, B_), dim3(32, 8)>>>();
    transpose_split_z<<<dim3(64, 8, B_), dim3(32, 8)>>>();
    // out[k,d] = Wt2[k,:] . Zt2[d,:] + lin_b[d]
    mma_gemm<0><<<dim3(16, 2, B_), 256>>>(pWt2, pZt2, out, lin_b,
                                          KI3, sWt, sZt, sOut, D_);
}